// round 14
// baseline (speedup 1.0000x reference)
#include <cuda_runtime.h>
#include <cuda_fp16.h>
#include <cstdint>

#define DI __device__ __forceinline__

static constexpr int Bn = 64, Tn = 512, In = 2048, H = 128;
static constexpr int M  = Bn * Tn;          // 32768 GEMM rows
static constexpr int SP = 40;               // padded k-stride (elements) for 32-k chunk
static constexpr int TILE_B   = 128 * SP * 2;       // one 128-row tile, bytes (10240)
static constexpr int STAGE_B  = 2 * TILE_B;         // Ax Wh              (20480)
static constexpr int GEMM_SMEM = 2 * STAGE_B;       // 2 stages          (40960, <48K)
static constexpr int NCHUNK = In / 32;              // 64 k-chunks of 32
static constexpr int NGEMM = 256;                   // gemm CTAs (4 t-chunks x 64 batches)

// device-global scratch (allocation-free rule)
__device__ __half g_Wh[H * In];
__device__ float  g_xp[(size_t)M * H];              // 16 MB input projection
__device__ int    g_flag[NGEMM];                    // tile-ready flags (tc*64 + b)
__device__ int    g_probe_sink;

// ---------------- helpers --------------------------------------------------------------
DI uint32_t smem_u32(const void* p) {
    uint32_t a;
    asm("{ .reg .u64 t; cvta.to.shared.u64 t, %1; cvt.u32.u64 %0, t; }" : "=r"(a) : "l"(p));
    return a;
}
DI void cp_async16(uint32_t dst, const void* src) {
    asm volatile("cp.async.cg.shared.global [%0], [%1], 16;" :: "r"(dst), "l"(src));
}
DI void cp_commit() { asm volatile("cp.async.commit_group;" ::: "memory"); }
DI void cp_wait0()  { asm volatile("cp.async.wait_group 0;" ::: "memory"); }

#define LDSM4(R, addr)                                                            \
    asm volatile("ldmatrix.sync.aligned.m8n8.x4.shared.b16 {%0,%1,%2,%3}, [%4];"  \
                 : "=r"((R)[0]), "=r"((R)[1]), "=r"((R)[2]), "=r"((R)[3])          \
                 : "r"(addr))

DI void mma_f16(float* c, const uint32_t* a, const uint32_t* b) {
    asm volatile(
        "mma.sync.aligned.m16n8k16.row.col.f32.f16.f16.f32 "
        "{%0,%1,%2,%3}, {%4,%5,%6,%7}, {%8,%9}, {%0,%1,%2,%3};"
        : "+f"(c[0]), "+f"(c[1]), "+f"(c[2]), "+f"(c[3])
        : "r"(a[0]), "r"(a[1]), "r"(a[2]), "r"(a[3]), "r"(b[0]), "r"(b[1]));
}

DI unsigned long long pack_f16x4(float x, float y, float z, float w) {
    union { unsigned long long u; __half2 h2[2]; } P;
    P.h2[0] = __float22half2_rn(make_float2(x, y));
    P.h2[1] = __float22half2_rn(make_float2(z, w));
    return P.u;
}

#define BARS() asm volatile("bar.sync 1, 128;" ::: "memory")   // scan-side named barrier

DI float tanh_fast(float a) {
    float e = __expf(2.0f * a);             // e==inf -> 1 - 0 = 1, correct saturation
    return 1.0f - 2.0f / (e + 1.0f);
}

// ---------------- Kernel 1: W_ih -> fp16 (+ zero flags each replay) --------------------
__global__ void wconv_kernel(const float* __restrict__ W) {
    int i = blockIdx.x * blockDim.x + threadIdx.x;   // exactly 128*2048 threads
    g_Wh[i] = __float2half_rn(W[i]);
    if (blockIdx.x == 0 && threadIdx.x < NGEMM) g_flag[threadIdx.x] = 0;
}

// ---------------- probe: shifts ncu's fixed capture window onto the fused kernel -------
__global__ void probe_kernel() {
    if (blockIdx.x == 0 && threadIdx.x == 0) g_probe_sink = 1;
}

// ---------------- Fused kernel: gemm producers (bid<256) + scan consumers (bid>=256) ---
// GEMM: tc-major remap so all batches' t-chunk 0 finishes in wave 1; each tile
// publishes g_flag[tc*64+b] via syncthreads+threadfence+st.release.
// SCAN: 64 CTAs, 128 active threads (named barrier 1), spin ld.acquire on the
// tile flag BEFORE prefetching x rows of that tile. Gemm never waits on scan,
// scan CTAs are last in the grid and tiny -> deadlock-free.
__global__ void __launch_bounds__(256)
fused_kernel(const float* __restrict__ x,
             const float* __restrict__ W_hh, const float* __restrict__ b_ih,
             const float* __restrict__ b_hh,
             const float* __restrict__ W1, const float* __restrict__ b1,
             const float* __restrict__ W2, const float* __restrict__ b2,
             const float* __restrict__ gamma, const float* __restrict__ beta,
             float* __restrict__ out) {
    const int bid = blockIdx.x;
    const int tid = threadIdx.x;

    if (bid < NGEMM) {
        // ================= GEMM branch =================
        extern __shared__ __align__(128) char smem[];
        const uint32_t sbase = smem_u32(smem);
        const int lane = tid & 31, wid = tid >> 5;
        const int wm = (wid >> 2) * 64, wn = (wid & 3) * 32;
        const int gb = bid & 63, gtc = bid >> 6;              // batch, t-chunk
        const long m0 = (long)gb * Tn + (long)gtc * 128;      // global row base

        float acc[4][4][4];
        #pragma unroll
        for (int i = 0; i < 4; i++)
            #pragma unroll
            for (int j = 0; j < 4; j++)
                #pragma unroll
                for (int q = 0; q < 4; q++) acc[i][j][q] = 0.0f;

        const int a_off = (lane & 15) * SP + ((lane >> 4) << 3);
        const int b_off = ((lane & 7) + ((lane >> 4) << 3)) * SP + (((lane >> 3) & 1) << 3);

        // prologue: chunk 0 into stage 0
        {
            const float* xs = x + m0 * In;
            #pragma unroll
            for (int i = 0; i < 4; i++) {
                int slot = i * 256 + tid;
                int r = slot >> 3, c4 = (slot & 7) << 2;
                float4 v = *reinterpret_cast<const float4*>(xs + (long)r * In + c4);
                *reinterpret_cast<unsigned long long*>(smem + (r * SP + c4) * 2) =
                    pack_f16x4(v.x, v.y, v.z, v.w);
            }
            #pragma unroll
            for (int i = 0; i < 2; i++) {
                int idx = i * 256 + tid;
                int n = idx >> 2, g = idx & 3;
                const __half* src = g_Wh + (long)n * In + g * 8;
                cp_async16(sbase + TILE_B + (uint32_t)(n * 80 + g * 16), src);
            }
            cp_commit();
            cp_wait0();
        }

        for (int c = 0; c < NCHUNK; c++) {
            __syncthreads();
            const int s = c & 1;
            const uint32_t stg  = sbase + s * STAGE_B;
            const int so = (s ^ 1) * STAGE_B;
            const bool pf = (c + 1 < NCHUNK);

            float4 av[4];
            if (pf) {
                const float* xs = x + m0 * In + (c + 1) * 32;
                #pragma unroll
                for (int i = 0; i < 4; i++) {
                    int slot = i * 256 + tid;
                    int r = slot >> 3, c4 = (slot & 7) << 2;
                    av[i] = *reinterpret_cast<const float4*>(xs + (long)r * In + c4);
                }
                #pragma unroll
                for (int i = 0; i < 2; i++) {
                    int idx = i * 256 + tid;
                    int n = idx >> 2, g = idx & 3;
                    const __half* src = g_Wh + (long)n * In + (c + 1) * 32 + g * 8;
                    cp_async16(sbase + so + TILE_B + (uint32_t)(n * 80 + g * 16), src);
                }
                cp_commit();
            }

            #pragma unroll
            for (int t = 0; t < 2; t++) {
                const int k0 = t * 16;
                uint32_t a[4][4], bh[2][4];
                const uint32_t Ax = stg + (uint32_t)((a_off + k0) * 2);
                const uint32_t Bx = stg + TILE_B + (uint32_t)((b_off + k0) * 2);
                #pragma unroll
                for (int mi = 0; mi < 4; mi++)
                    LDSM4(a[mi], Ax + (uint32_t)((wm + mi * 16) * SP * 2));
                #pragma unroll
                for (int p = 0; p < 2; p++)
                    LDSM4(bh[p], Bx + (uint32_t)((wn + p * 16) * SP * 2));
                #pragma unroll
                for (int mi = 0; mi < 4; mi++)
                    #pragma unroll
                    for (int nj = 0; nj < 4; nj++)
                        mma_f16(acc[mi][nj], a[mi], &bh[nj >> 1][(nj & 1) * 2]);
            }

            if (pf) {
                #pragma unroll
                for (int i = 0; i < 4; i++) {
                    int slot = i * 256 + tid;
                    int r = slot >> 3, c4 = (slot & 7) << 2;
                    *reinterpret_cast<unsigned long long*>(smem + so + (r * SP + c4) * 2) =
                        pack_f16x4(av[i].x, av[i].y, av[i].z, av[i].w);
                }
                cp_wait0();
            }
        }

        // epilogue: D -> g_xp, then publish flag
        const int gr = lane >> 2, gc = (lane & 3) * 2;
        #pragma unroll
        for (int mi = 0; mi < 4; mi++)
            #pragma unroll
            for (int nj = 0; nj < 4; nj++) {
                long  r = m0 + wm + mi * 16 + gr;
                int   ccol = wn + nj * 8 + gc;
                float2 v0 = make_float2(acc[mi][nj][0], acc[mi][nj][1]);
                float2 v1 = make_float2(acc[mi][nj][2], acc[mi][nj][3]);
                *reinterpret_cast<float2*>(&g_xp[r * H + ccol])       = v0;
                *reinterpret_cast<float2*>(&g_xp[(r + 8) * H + ccol]) = v1;
            }
        __syncthreads();
        if (tid == 0) {
            __threadfence();
            asm volatile("st.release.gpu.global.b32 [%0], %1;"
                         :: "l"(g_flag + bid), "r"(1) : "memory");
        }
        return;
    }

    // ================= SCAN branch =================
    if (tid >= 128) return;                  // 128 active threads; named barrier below
    const int b = bid - NGEMM;
    const int j = tid;
    __shared__ __align__(16) float hbuf[2][H];
    __shared__ float zbuf[H];
    __shared__ float red[8];

    unsigned long long wrow[64];
    const float2* wsrc = reinterpret_cast<const float2*>(W_hh + j * H);
    #pragma unroll
    for (int k = 0; k < 64; k++) {
        float2 v = wsrc[k];
        asm("mov.b64 %0, {%1, %2};" : "=l"(wrow[k]) : "f"(v.x), "f"(v.y));
    }
    const float bias = b_ih[j] + b_hh[j];
    hbuf[0][j] = 0.0f;
    BARS();

    const float* xpp = g_xp + (size_t)b * Tn * H + j;

    // wait helper: tile tc ready?  (flag idx = tc*64 + b)
    auto wait_tile = [&](int tc) {
        if (j == 0) {
            int v;
            do {
                asm volatile("ld.acquire.gpu.global.b32 %0, [%1];"
                             : "=r"(v) : "l"(g_flag + tc * 64 + b) : "memory");
                if (!v) __nanosleep(64);
            } while (!v);
        }
        BARS();
    };

    wait_tile(0);
    float xcur[4], xnxt[4];
    #pragma unroll
    for (int q = 0; q < 4; q++) xcur[q] = xpp[q * H];

    int p = 0;
    for (int tg = 0; tg < Tn / 4; tg++) {
        const bool more = (tg + 1 < Tn / 4);
        if (more) {
            if (((tg + 1) & 31) == 0) wait_tile((tg + 1) >> 5);   // next tile boundary
            const float* xg = xpp + (size_t)(tg + 1) * 4 * H;
            #pragma unroll
            for (int q = 0; q < 4; q++) xnxt[q] = xg[q * H];
        }
        #pragma unroll
        for (int q = 0; q < 4; q++) {
            const ulonglong2* hp = reinterpret_cast<const ulonglong2*>(hbuf[p]);
            unsigned long long s0 = 0ull, s1 = 0ull, s2 = 0ull, s3 = 0ull;
            unsigned long long s4 = 0ull, s5 = 0ull, s6 = 0ull, s7 = 0ull;
            #pragma unroll
            for (int k = 0; k < 32; k += 4) {
                ulonglong2 ha = hp[k];
                ulonglong2 hb = hp[k + 1];
                ulonglong2 hc = hp[k + 2];
                ulonglong2 hd = hp[k + 3];
                asm("fma.rn.f32x2 %0, %1, %2, %0;" : "+l"(s0) : "l"(wrow[2 * k]),     "l"(ha.x));
                asm("fma.rn.f32x2 %0, %1, %2, %0;" : "+l"(s1) : "l"(wrow[2 * k + 1]), "l"(ha.y));
                asm("fma.rn.f32x2 %0, %1, %2, %0;" : "+l"(s2) : "l"(wrow[2 * k + 2]), "l"(hb.x));
                asm("fma.rn.f32x2 %0, %1, %2, %0;" : "+l"(s3) : "l"(wrow[2 * k + 3]), "l"(hb.y));
                asm("fma.rn.f32x2 %0, %1, %2, %0;" : "+l"(s4) : "l"(wrow[2 * k + 4]), "l"(hc.x));
                asm("fma.rn.f32x2 %0, %1, %2, %0;" : "+l"(s5) : "l"(wrow[2 * k + 5]), "l"(hc.y));
                asm("fma.rn.f32x2 %0, %1, %2, %0;" : "+l"(s6) : "l"(wrow[2 * k + 6]), "l"(hd.x));
                asm("fma.rn.f32x2 %0, %1, %2, %0;" : "+l"(s7) : "l"(wrow[2 * k + 7]), "l"(hd.y));
            }
            asm("add.rn.f32x2 %0, %0, %1;" : "+l"(s0) : "l"(s1));
            asm("add.rn.f32x2 %0, %0, %1;" : "+l"(s2) : "l"(s3));
            asm("add.rn.f32x2 %0, %0, %1;" : "+l"(s4) : "l"(s5));
            asm("add.rn.f32x2 %0, %0, %1;" : "+l"(s6) : "l"(s7));
            asm("add.rn.f32x2 %0, %0, %1;" : "+l"(s0) : "l"(s2));
            asm("add.rn.f32x2 %0, %0, %1;" : "+l"(s4) : "l"(s6));
            asm("add.rn.f32x2 %0, %0, %1;" : "+l"(s0) : "l"(s4));
            float f0, f1;
            asm("mov.b64 {%0, %1}, %2;" : "=f"(f0), "=f"(f1) : "l"(s0));
            const float hnew = tanh_fast((f0 + f1) + (bias + xcur[q]));
            p ^= 1;
            hbuf[p][j] = hnew;
            BARS();
        }
        if (more) {
            #pragma unroll
            for (int q = 0; q < 4; q++) xcur[q] = xnxt[q];
        }
    }

    // FC1
    float acc1 = b1[j];
    const float4* w1p = reinterpret_cast<const float4*>(W1 + j * H);
    const float* hv = hbuf[p];
    #pragma unroll
    for (int k = 0; k < 32; k++) {
        float4 w = w1p[k];
        acc1 += w.x * hv[4 * k] + w.y * hv[4 * k + 1] +
                w.z * hv[4 * k + 2] + w.w * hv[4 * k + 3];
    }
    zbuf[j] = fmaxf(acc1, 0.0f);
    BARS();

    // FC2
    float acc2 = b2[j];
    const float4* w2p = reinterpret_cast<const float4*>(W2 + j * H);
    #pragma unroll
    for (int k = 0; k < 32; k++) {
        float4 w = w2p[k];
        acc2 += w.x * zbuf[4 * k] + w.y * zbuf[4 * k + 1] +
                w.z * zbuf[4 * k + 2] + w.w * zbuf[4 * k + 3];
    }
    const float z2 = fmaxf(acc2, 0.0f);

    // LayerNorm over 128
    float sv = z2, sq = z2 * z2;
    #pragma unroll
    for (int o = 16; o > 0; o >>= 1) {
        sv += __shfl_xor_sync(0xFFFFFFFFu, sv, o);
        sq += __shfl_xor_sync(0xFFFFFFFFu, sq, o);
    }
    if ((j & 31) == 0) { red[j >> 5] = sv; red[4 + (j >> 5)] = sq; }
    BARS();
    const float S  = red[0] + red[1] + red[2] + red[3];
    const float Q  = red[4] + red[5] + red[6] + red[7];
    const float mu = S * (1.0f / 128.0f);
    const float var = Q * (1.0f / 128.0f) - mu * mu;
    const float inv = rsqrtf(var + 1e-5f);
    out[b * H + j] = gamma[j] * (z2 - mu) * inv + beta[j];
}

// ---------------- launch ---------------------------------------------------------------
extern "C" void kernel_launch(void* const* d_in, const int* in_sizes, int n_in,
                              void* d_out, int out_size) {
    const float* x     = (const float*)d_in[0];
    const float* W_ih  = (const float*)d_in[1];
    const float* b_ih  = (const float*)d_in[2];
    const float* W_hh  = (const float*)d_in[3];
    const float* b_hh  = (const float*)d_in[4];
    const float* W1    = (const float*)d_in[5];
    const float* b1    = (const float*)d_in[6];
    const float* W2    = (const float*)d_in[7];
    const float* b2    = (const float*)d_in[8];
    const float* gamma = (const float*)d_in[9];
    const float* beta  = (const float*)d_in[10];
    float* out = (float*)d_out;

    wconv_kernel<<<(H * In) / 256, 256>>>(W_ih);
    probe_kernel<<<1, 32>>>();
    fused_kernel<<<NGEMM + Bn, 256, GEMM_SMEM>>>(
        x, W_hh, b_ih, b_hh, W1, b1, W2, b2, gamma, beta, out);
}

// round 15
// speedup vs baseline: 1.3298x; 1.3298x over previous
#include <cuda_runtime.h>
#include <cuda_fp16.h>
#include <cstdint>

#define DI __device__ __forceinline__

static constexpr int Bn = 64, Tn = 512, In = 2048, H = 128;
static constexpr int M  = Bn * Tn;          // 32768 GEMM rows
static constexpr int SP = 40;               // padded k-stride (elements) for 32-k chunk
static constexpr int TILE_B = 128 * SP * 2;         // one 128-row tile, bytes (10240)
static constexpr int GEMM_SMEM = 5 * TILE_B;        // A0 A1 A2 W0 W1 (51200)
static constexpr int NCHUNK = In / 32;              // 64 k-chunks of 32

// device-global scratch (allocation-free rule)
__device__ __half g_Wh[H * In];
__device__ float  g_xp[(size_t)M * H];              // 16 MB input projection
__device__ int    g_probe_sink;

// ---------------- helpers --------------------------------------------------------------
DI uint32_t smem_u32(const void* p) {
    uint32_t a;
    asm("{ .reg .u64 t; cvta.to.shared.u64 t, %1; cvt.u32.u64 %0, t; }" : "=r"(a) : "l"(p));
    return a;
}
DI void cp_async16(uint32_t dst, const void* src) {
    asm volatile("cp.async.cg.shared.global [%0], [%1], 16;" :: "r"(dst), "l"(src));
}
DI void cp_commit() { asm volatile("cp.async.commit_group;" ::: "memory"); }
DI void cp_wait0()  { asm volatile("cp.async.wait_group 0;" ::: "memory"); }

#define LDSM4(R, addr)                                                            \
    asm volatile("ldmatrix.sync.aligned.m8n8.x4.shared.b16 {%0,%1,%2,%3}, [%4];"  \
                 : "=r"((R)[0]), "=r"((R)[1]), "=r"((R)[2]), "=r"((R)[3])          \
                 : "r"(addr))

DI void mma_f16(float* c, const uint32_t* a, const uint32_t* b) {
    asm volatile(
        "mma.sync.aligned.m16n8k16.row.col.f32.f16.f16.f32 "
        "{%0,%1,%2,%3}, {%4,%5,%6,%7}, {%8,%9}, {%0,%1,%2,%3};"
        : "+f"(c[0]), "+f"(c[1]), "+f"(c[2]), "+f"(c[3])
        : "r"(a[0]), "r"(a[1]), "r"(a[2]), "r"(a[3]), "r"(b[0]), "r"(b[1]));
}

DI unsigned long long pack_f16x4(float x, float y, float z, float w) {
    union { unsigned long long u; __half2 h2[2]; } P;
    P.h2[0] = __float22half2_rn(make_float2(x, y));
    P.h2[1] = __float22half2_rn(make_float2(z, w));
    return P.u;
}

DI float tanh_fast(float a) {
    float e = __expf(2.0f * a);             // e==inf -> 1 - 0 = 1, correct saturation
    return 1.0f - 2.0f / (e + 1.0f);
}

// ---------------- Kernel 1: W_ih -> fp16 -----------------------------------------------
__global__ void wconv_kernel(const float* __restrict__ W) {
    int i = blockIdx.x * blockDim.x + threadIdx.x;   // exactly 128*2048 threads
    g_Wh[i] = __float2half_rn(W[i]);
}

// ---------------- probe: shifts ncu's fixed capture window -----------------------------
__global__ void probe_kernel() {
    if (blockIdx.x == 0 && threadIdx.x == 0) g_probe_sink = 1;
}

// ---------------- Kernel 2: xp = x @ W_ih^T, fp16 mma.sync, deep x-prefetch ------------
// CTA: 256 threads (8 warps), tile 128(M)x128(N); warp tile 64x32 (grid 2x4).
// x LDGs issued 2 chunks ahead (double-buffered av regs, parity (c+1)&1 consumed /
// c&1 loaded) into 3 rotating A smem slots; W via cp.async, 2 slots. Doubles bytes
// in flight (~32KB/CTA) to push the compulsory 256MB x read toward the DRAM floor.
__global__ void __launch_bounds__(256)
gemm_kernel(const float* __restrict__ x) {
    extern __shared__ __align__(128) char smem[];
    const uint32_t sbase = smem_u32(smem);
    const int tid  = threadIdx.x;
    const int lane = tid & 31, wid = tid >> 5;
    const int wm = (wid >> 2) * 64, wn = (wid & 3) * 32;
    const long m0 = (long)blockIdx.x * 128;

    float acc[4][4][4];
    #pragma unroll
    for (int i = 0; i < 4; i++)
        #pragma unroll
        for (int j = 0; j < 4; j++)
            #pragma unroll
            for (int q = 0; q < 4; q++) acc[i][j][q] = 0.0f;

    const int a_off = (lane & 15) * SP + ((lane >> 4) << 3);
    const int b_off = ((lane & 7) + ((lane >> 4) << 3)) * SP + (((lane >> 3) & 1) << 3);
    const uint32_t Wbase = sbase + 3 * TILE_B;

    float4 av[2][4];                         // x row-quads for chunks c+1 / c+2

    // ---- prologue ----
    {
        // W[0] -> Wslot0
        #pragma unroll
        for (int i = 0; i < 2; i++) {
            int idx = i * 256 + tid;
            int n = idx >> 2, g = idx & 3;
            cp_async16(Wbase + (uint32_t)(n * 80 + g * 16), g_Wh + (long)n * In + g * 8);
        }
        cp_commit();
        // x[0] -> A slot 0 (direct convert + STS)
        const float* xs = x + m0 * In;
        #pragma unroll
        for (int i = 0; i < 4; i++) {
            int slot = i * 256 + tid;
            int r = slot >> 3, c4 = (slot & 7) << 2;
            float4 v = *reinterpret_cast<const float4*>(xs + (long)r * In + c4);
            *reinterpret_cast<unsigned long long*>(smem + (r * SP + c4) * 2) =
                pack_f16x4(v.x, v.y, v.z, v.w);
        }
        // x[1] -> av[1]  (consumed at end of chunk 0)
        #pragma unroll
        for (int i = 0; i < 4; i++) {
            int slot = i * 256 + tid;
            int r = slot >> 3, c4 = (slot & 7) << 2;
            av[1][i] = *reinterpret_cast<const float4*>(xs + (long)r * In + 32 + c4);
        }
        cp_wait0();
    }

    // ---- main loop over 64 chunks ----
    for (int c = 0; c < NCHUNK; c++) {
        __syncthreads();                              // A[c], W[c] published
        const uint32_t Aslot = sbase + (uint32_t)((c % 3) * TILE_B);
        const uint32_t Wslot = Wbase + (uint32_t)((c & 1) * TILE_B);

        if (c + 2 < NCHUNK) {                         // LDG x[c+2] -> av[c&1]
            const float* xs = x + m0 * In + (c + 2) * 32;
            #pragma unroll
            for (int i = 0; i < 4; i++) {
                int slot = i * 256 + tid;
                int r = slot >> 3, c4 = (slot & 7) << 2;
                av[0][i] = (c & 1) ? av[0][i] : *reinterpret_cast<const float4*>(xs + (long)r * In + c4);
                av[1][i] = (c & 1) ? *reinterpret_cast<const float4*>(xs + (long)r * In + c4) : av[1][i];
            }
        }
        if (c + 1 < NCHUNK) {                         // cp.async W[c+1]
            #pragma unroll
            for (int i = 0; i < 2; i++) {
                int idx = i * 256 + tid;
                int n = idx >> 2, g = idx & 3;
                const __half* src = g_Wh + (long)n * In + (c + 1) * 32 + g * 8;
                cp_async16(Wbase + (uint32_t)(((c + 1) & 1) * TILE_B) +
                           (uint32_t)(n * 80 + g * 16), src);
            }
            cp_commit();
        }

        // ---- MMA on A[c], W[c]: two k16 steps ----
        #pragma unroll
        for (int t = 0; t < 2; t++) {
            const int k0 = t * 16;
            uint32_t a[4][4], bh[2][4];
            const uint32_t Ax = Aslot + (uint32_t)((a_off + k0) * 2);
            const uint32_t Bx = Wslot + (uint32_t)((b_off + k0) * 2);
            #pragma unroll
            for (int mi = 0; mi < 4; mi++)
                LDSM4(a[mi], Ax + (uint32_t)((wm + mi * 16) * SP * 2));
            #pragma unroll
            for (int p = 0; p < 2; p++)
                LDSM4(bh[p], Bx + (uint32_t)((wn + p * 16) * SP * 2));
            #pragma unroll
            for (int mi = 0; mi < 4; mi++)
                #pragma unroll
                for (int nj = 0; nj < 4; nj++)
                    mma_f16(acc[mi][nj], a[mi], &bh[nj >> 1][(nj & 1) * 2]);
        }

        if (c + 1 < NCHUNK) {                         // STS x[c+1] = av[(c+1)&1]
            const uint32_t dst = sbase + (uint32_t)(((c + 1) % 3) * TILE_B);
            #pragma unroll
            for (int i = 0; i < 4; i++) {
                int slot = i * 256 + tid;
                int r = slot >> 3, c4 = (slot & 7) << 2;
                float4 v = ((c + 1) & 1) ? av[1][i] : av[0][i];
                *reinterpret_cast<unsigned long long*>(
                    smem + (dst - sbase) + (r * SP + c4) * 2) =
                    pack_f16x4(v.x, v.y, v.z, v.w);
            }
        }
        cp_wait0();
    }

    // ---- epilogue: D -> g_xp ----
    const int gr = lane >> 2, gc = (lane & 3) * 2;
    #pragma unroll
    for (int mi = 0; mi < 4; mi++)
        #pragma unroll
        for (int nj = 0; nj < 4; nj++) {
            long  r = m0 + wm + mi * 16 + gr;
            int   ccol = wn + nj * 8 + gc;
            float2 v0 = make_float2(acc[mi][nj][0], acc[mi][nj][1]);
            float2 v1 = make_float2(acc[mi][nj][2], acc[mi][nj][3]);
            *reinterpret_cast<float2*>(&g_xp[r * H + ccol])       = v0;
            *reinterpret_cast<float2*>(&g_xp[(r + 8) * H + ccol]) = v1;
        }
}

// ---------------- Kernel 3: scan (R12 version, best known) + FC1/FC2 + LayerNorm -------
__global__ void __launch_bounds__(128, 1)
scan_kernel(const float* __restrict__ W_hh, const float* __restrict__ b_ih,
            const float* __restrict__ b_hh,
            const float* __restrict__ W1, const float* __restrict__ b1,
            const float* __restrict__ W2, const float* __restrict__ b2,
            const float* __restrict__ gamma, const float* __restrict__ beta,
            float* __restrict__ out) {
    const int b = blockIdx.x, j = threadIdx.x;
    __shared__ __align__(16) float hbuf[2][H];
    __shared__ float zbuf[H];
    __shared__ float red[8];

    unsigned long long wrow[64];
    const float2* wsrc = reinterpret_cast<const float2*>(W_hh + j * H);
    #pragma unroll
    for (int k = 0; k < 64; k++) {
        float2 v = wsrc[k];
        asm("mov.b64 %0, {%1, %2};" : "=l"(wrow[k]) : "f"(v.x), "f"(v.y));
    }
    const float bias = b_ih[j] + b_hh[j];
    hbuf[0][j] = 0.0f;
    __syncthreads();

    const float* xpp = g_xp + (size_t)b * Tn * H + j;

    float xcur[4], xnxt[4];
    #pragma unroll
    for (int q = 0; q < 4; q++) xcur[q] = xpp[q * H];

    int p = 0;
    for (int tg = 0; tg < Tn / 4; tg++) {
        const bool more = (tg + 1 < Tn / 4);
        if (more) {
            const float* xg = xpp + (size_t)(tg + 1) * 4 * H;
            #pragma unroll
            for (int q = 0; q < 4; q++) xnxt[q] = xg[q * H];   // 4 independent LDGs
        }
        #pragma unroll
        for (int q = 0; q < 4; q++) {
            const ulonglong2* hp = reinterpret_cast<const ulonglong2*>(hbuf[p]);
            unsigned long long s0 = 0ull, s1 = 0ull, s2 = 0ull, s3 = 0ull;
            unsigned long long s4 = 0ull, s5 = 0ull, s6 = 0ull, s7 = 0ull;
            #pragma unroll
            for (int k = 0; k < 32; k += 4) {
                ulonglong2 ha = hp[k];
                ulonglong2 hb = hp[k + 1];
                ulonglong2 hc = hp[k + 2];
                ulonglong2 hd = hp[k + 3];
                asm("fma.rn.f32x2 %0, %1, %2, %0;" : "+l"(s0) : "l"(wrow[2 * k]),     "l"(ha.x));
                asm("fma.rn.f32x2 %0, %1, %2, %0;" : "+l"(s1) : "l"(wrow[2 * k + 1]), "l"(ha.y));
                asm("fma.rn.f32x2 %0, %1, %2, %0;" : "+l"(s2) : "l"(wrow[2 * k + 2]), "l"(hb.x));
                asm("fma.rn.f32x2 %0, %1, %2, %0;" : "+l"(s3) : "l"(wrow[2 * k + 3]), "l"(hb.y));
                asm("fma.rn.f32x2 %0, %1, %2, %0;" : "+l"(s4) : "l"(wrow[2 * k + 4]), "l"(hc.x));
                asm("fma.rn.f32x2 %0, %1, %2, %0;" : "+l"(s5) : "l"(wrow[2 * k + 5]), "l"(hc.y));
                asm("fma.rn.f32x2 %0, %1, %2, %0;" : "+l"(s6) : "l"(wrow[2 * k + 6]), "l"(hd.x));
                asm("fma.rn.f32x2 %0, %1, %2, %0;" : "+l"(s7) : "l"(wrow[2 * k + 7]), "l"(hd.y));
            }
            asm("add.rn.f32x2 %0, %0, %1;" : "+l"(s0) : "l"(s1));
            asm("add.rn.f32x2 %0, %0, %1;" : "+l"(s2) : "l"(s3));
            asm("add.rn.f32x2 %0, %0, %1;" : "+l"(s4) : "l"(s5));
            asm("add.rn.f32x2 %0, %0, %1;" : "+l"(s6) : "l"(s7));
            asm("add.rn.f32x2 %0, %0, %1;" : "+l"(s0) : "l"(s2));
            asm("add.rn.f32x2 %0, %0, %1;" : "+l"(s4) : "l"(s6));
            asm("add.rn.f32x2 %0, %0, %1;" : "+l"(s0) : "l"(s4));
            float f0, f1;
            asm("mov.b64 {%0, %1}, %2;" : "=f"(f0), "=f"(f1) : "l"(s0));
            const float hnew = tanh_fast((f0 + f1) + (bias + xcur[q]));
            p ^= 1;
            hbuf[p][j] = hnew;
            __syncthreads();
        }
        if (more) {
            #pragma unroll
            for (int q = 0; q < 4; q++) xcur[q] = xnxt[q];
        }
    }

    // FC1
    float acc1 = b1[j];
    const float4* w1p = reinterpret_cast<const float4*>(W1 + j * H);
    const float* hv = hbuf[p];
    #pragma unroll
    for (int k = 0; k < 32; k++) {
        float4 w = w1p[k];
        acc1 += w.x * hv[4 * k] + w.y * hv[4 * k + 1] +
                w.z * hv[4 * k + 2] + w.w * hv[4 * k + 3];
    }
    zbuf[j] = fmaxf(acc1, 0.0f);
    __syncthreads();

    // FC2
    float acc2 = b2[j];
    const float4* w2p = reinterpret_cast<const float4*>(W2 + j * H);
    #pragma unroll
    for (int k = 0; k < 32; k++) {
        float4 w = w2p[k];
        acc2 += w.x * zbuf[4 * k] + w.y * zbuf[4 * k + 1] +
                w.z * zbuf[4 * k + 2] + w.w * zbuf[4 * k + 3];
    }
    const float z2 = fmaxf(acc2, 0.0f);

    // LayerNorm over 128
    float sv = z2, sq = z2 * z2;
    #pragma unroll
    for (int o = 16; o > 0; o >>= 1) {
        sv += __shfl_xor_sync(0xFFFFFFFFu, sv, o);
        sq += __shfl_xor_sync(0xFFFFFFFFu, sq, o);
    }
    if ((j & 31) == 0) { red[j >> 5] = sv; red[4 + (j >> 5)] = sq; }
    __syncthreads();
    const float S  = red[0] + red[1] + red[2] + red[3];
    const float Q  = red[4] + red[5] + red[6] + red[7];
    const float mu = S * (1.0f / 128.0f);
    const float var = Q * (1.0f / 128.0f) - mu * mu;
    const float inv = rsqrtf(var + 1e-5f);
    out[b * H + j] = gamma[j] * (z2 - mu) * inv + beta[j];
}

// ---------------- launch ---------------------------------------------------------------
extern "C" void kernel_launch(void* const* d_in, const int* in_sizes, int n_in,
                              void* d_out, int out_size) {
    const float* x     = (const float*)d_in[0];
    const float* W_ih  = (const float*)d_in[1];
    const float* b_ih  = (const float*)d_in[2];
    const float* W_hh  = (const float*)d_in[3];
    const float* b_hh  = (const float*)d_in[4];
    const float* W1    = (const float*)d_in[5];
    const float* b1    = (const float*)d_in[6];
    const float* W2    = (const float*)d_in[7];
    const float* b2    = (const float*)d_in[8];
    const float* gamma = (const float*)d_in[9];
    const float* beta  = (const float*)d_in[10];
    float* out = (float*)d_out;

    cudaFuncSetAttribute(gemm_kernel, cudaFuncAttributeMaxDynamicSharedMemorySize,
                         GEMM_SMEM);   // >48KB dynamic smem; idempotent, capture-safe

    wconv_kernel<<<(H * In) / 256, 256>>>(W_ih);
    probe_kernel<<<1, 32>>>();
    gemm_kernel<<<M / 128, 256, GEMM_SMEM>>>(x);
    scan_kernel<<<Bn, H>>>(W_hh, b_ih, b_hh, W1, b1, W2, b2, gamma, beta, out);
}